// round 4
// baseline (speedup 1.0000x reference)
#include <cuda_runtime.h>

#define NB    256
#define NS    64
#define KACT  8
#define INF_  1024
#define OUTF  1024
#define SUBF  128
#define QF    1024

// ---------------- device scratch (static globals: no runtime allocation) ----------
__device__ int   g_cnt[NS];
__device__ int   g_off[NS];
__device__ int   g_sel_s[NB * KACT];
__device__ float g_sel_w[NB * KACT];
__device__ int   g_asg_b[NB * KACT];          // compacted: batch row per assignment
__device__ float g_asg_w[NB * KACT];          // compacted: softmax weight per assignment
__device__ int   g_map[NB * KACT];            // (b,slot) -> compact index
__device__ int   g_work[NB * KACT / 8 + NS];  // (subnet<<8)|chunk work items
__device__ int   g_nwork;
__device__ float g_T[(NB * KACT + 8) * SUBF]; // stage-1 output (weight pre-applied)
__device__ float g_opart[NB * KACT * OUTF];   // 8 MB partial outputs

// ---------------- cp.async helpers ------------------------------------------------
__device__ __forceinline__ void cp16(void* s, const void* g) {
    unsigned sa = (unsigned)__cvta_generic_to_shared(s);
    asm volatile("cp.async.cg.shared.global [%0], [%1], 16;\n" :: "r"(sa), "l"(g));
}
#define CP_COMMIT()  asm volatile("cp.async.commit_group;\n")
#define CP_WAIT(n)   asm volatile("cp.async.wait_group %0;\n" :: "n"(n))

// ---------------- kernel 1: attention + top-8 + softmax --------------------------
// 32 CTAs x 256 threads, 8 batch rows per CTA. No global atomics.
__global__ void __launch_bounds__(256) colak_attn(const float* __restrict__ q,
                                                  const float* __restrict__ Wk,
                                                  const float* __restrict__ bk) {
    __shared__ float qs[8 * QF];      // 32 KB
    __shared__ float att[8][NS];
    const int b0   = blockIdx.x * 8;
    const int tid  = threadIdx.x;
    const int w    = tid >> 5;
    const int lane = tid & 31;

    for (int f = tid; f < 8 * (QF / 4); f += 256)
        ((float4*)qs)[f] = ((const float4*)(q + (size_t)b0 * QF))[f];
    __syncthreads();

    const float4* q4 = (const float4*)qs;
    #pragma unroll
    for (int p = 0; p < 8; p++) {
        const int s = p * 8 + w;
        const float4* wr = (const float4*)(Wk + (size_t)s * QF);
        float acc[8];
        #pragma unroll
        for (int r = 0; r < 8; r++) acc[r] = 0.f;
        #pragma unroll
        for (int i = lane; i < QF / 4; i += 32) {
            float4 a = wr[i];
            #pragma unroll
            for (int r = 0; r < 8; r++) {
                float4 c = q4[r * (QF / 4) + i];
                acc[r] += a.x * c.x + a.y * c.y + a.z * c.z + a.w * c.w;
            }
        }
        #pragma unroll
        for (int r = 0; r < 8; r++) {
            float v = acc[r];
            #pragma unroll
            for (int o = 16; o; o >>= 1) v += __shfl_xor_sync(0xffffffffu, v, o);
            if (lane == 0) att[r][s] = v + bk[s];
        }
    }
    __syncthreads();

    if (w < 8) {   // warp w handles batch row b0+w
        const int b = b0 + w;
        float v0 = att[w][lane], v1 = att[w][lane + 32];
        int r0 = 0, r1 = 0;
        #pragma unroll
        for (int j = 0; j < NS; j++) {
            float a = att[w][j];
            r0 += (a > v0) || (a == v0 && j < lane);
            r1 += (a > v1) || (a == v1 && j < lane + 32);
        }
        bool k0 = r0 < KACT, k1 = r1 < KACT;

        float m = fmaxf(k0 ? v0 : -1e30f, k1 ? v1 : -1e30f);
        #pragma unroll
        for (int o = 16; o; o >>= 1) m = fmaxf(m, __shfl_xor_sync(0xffffffffu, m, o));

        float e0 = k0 ? expf(v0 - m) : 0.f;
        float e1 = k1 ? expf(v1 - m) : 0.f;
        float sm = e0 + e1;
        #pragma unroll
        for (int o = 16; o; o >>= 1) sm += __shfl_xor_sync(0xffffffffu, sm, o);

        unsigned m0 = __ballot_sync(0xffffffffu, k0);
        unsigned m1 = __ballot_sync(0xffffffffu, k1);
        unsigned lt = (1u << lane) - 1u;
        int base1 = __popc(m0);
        if (k0) {
            int slot = __popc(m0 & lt);
            g_sel_s[b * KACT + slot] = lane;
            g_sel_w[b * KACT + slot] = e0 / sm;
        }
        if (k1) {
            int slot = base1 + __popc(m1 & lt);
            g_sel_s[b * KACT + slot] = lane + 32;
            g_sel_w[b * KACT + slot] = e1 / sm;
        }
    }
}

// ---------------- kernel 2: count + prefix + compact + work list (one block) ------
__global__ void __launch_bounds__(256) colak_scatter() {
    __shared__ int cnt[NS], off_s[NS], fill[NS];
    const int tid = threadIdx.x;
    if (tid < NS) cnt[tid] = 0;
    __syncthreads();
    for (int idx = tid; idx < NB * KACT; idx += 256)
        atomicAdd(&cnt[g_sel_s[idx]], 1);
    __syncthreads();
    if (tid == 0) {
        int run = 0, k = 0;
        for (int s = 0; s < NS; s++) {
            off_s[s] = run; run += cnt[s];
            int nc = (cnt[s] + 7) >> 3;
            for (int c = 0; c < nc; c++) g_work[k++] = (s << 8) | c;
        }
        g_nwork = k;
    }
    __syncthreads();
    if (tid < NS) { g_cnt[tid] = cnt[tid]; g_off[tid] = off_s[tid]; fill[tid] = off_s[tid]; }
    __syncthreads();
    for (int idx = tid; idx < NB * KACT; idx += 256) {
        int s = g_sel_s[idx];
        int p = atomicAdd(&fill[s], 1);
        g_asg_b[p] = idx >> 3;
        g_asg_w[p] = g_sel_w[idx];
        g_map[idx] = p;
    }
}

// ---------------- kernel T: stage 1  T[r][j] = wt[r] * sum_i X[r][i]*V0[s][j][i] ---
// work-queue driven, 128 threads, 8 rows per item. Both V0 and X tiles stream
// through double-buffered cp.async. smem = 2 x (128+8) x 68 floats = 74 KB.
#define TP 68
#define T_BUF_FLOATS (136 * TP)
#define SMEM_T_BYTES (2 * T_BUF_FLOATS * 4)
#define T_GRID (NB * KACT / 8 + NS)

__global__ void __launch_bounds__(128) colak_T(const float* __restrict__ x,
                                               const float* __restrict__ V0) {
    if ((int)blockIdx.x >= g_nwork) return;
    const int item = g_work[blockIdx.x];
    const int s = item >> 8;
    const int c = item & 255;
    const int n = g_cnt[s];
    const int m = min(8, n - c * 8);
    const int gbase = g_off[s] + c * 8;

    extern __shared__ float smem[];     // buf b: V rows [0..127], X rows [128..135]
    __shared__ int   rows[8];
    __shared__ float wts[8];

    const int tid  = threadIdx.x;
    const int w    = tid >> 5;
    const int lane = tid & 31;
    const int j    = w * 32 + lane;   // 0..127

    if (tid < 8) {
        rows[tid] = (tid < m) ? g_asg_b[gbase + tid] : 0;
        wts[tid]  = (tid < m) ? g_asg_w[gbase + tid] : 0.f;
    }
    __syncthreads();

    const float* v0 = V0 + (size_t)s * SUBF * INF_;
    const int xr_ = tid >> 4, xs_ = tid & 15;   // X tile is 8 rows x 64 floats: 1 cp16/thread
    const float* xrow = x + (size_t)rows[xr_] * INF_;

    // prefetch tile 0
    {
        float* dst = smem;
        #pragma unroll
        for (int k = 0; k < 16; k++) {
            int idx = k * 128 + tid;
            int jr = idx >> 4, seg = idx & 15;
            cp16(dst + jr * TP + seg * 4, v0 + (size_t)jr * INF_ + seg * 4);
        }
        cp16(dst + (128 + xr_) * TP + xs_ * 4, xrow + xs_ * 4);
        CP_COMMIT();
    }

    float acc[8];
    #pragma unroll
    for (int r = 0; r < 8; r++) acc[r] = 0.f;

    for (int it = 0; it < 16; it++) {
        float* buf = smem + (it & 1) * T_BUF_FLOATS;
        if (it + 1 < 16) {
            float* dst = smem + ((it + 1) & 1) * T_BUF_FLOATS;
            const float* src = v0 + (it + 1) * 64;
            #pragma unroll
            for (int k = 0; k < 16; k++) {
                int idx = k * 128 + tid;
                int jr = idx >> 4, seg = idx & 15;
                cp16(dst + jr * TP + seg * 4, src + (size_t)jr * INF_ + seg * 4);
            }
            cp16(dst + (128 + xr_) * TP + xs_ * 4, xrow + (it + 1) * 64 + xs_ * 4);
            CP_COMMIT();
            CP_WAIT(1);
        } else {
            CP_WAIT(0);
        }
        __syncthreads();

        const float* vr = buf + j * TP;
        const float* xb = buf + 128 * TP;
        #pragma unroll
        for (int i4 = 0; i4 < 16; i4++) {
            float4 v = *(const float4*)(vr + (i4 << 2));
            #pragma unroll
            for (int r = 0; r < 8; r++) {
                float4 xx = *(const float4*)(xb + r * TP + (i4 << 2));  // broadcast
                acc[r] += v.x * xx.x + v.y * xx.y + v.z * xx.z + v.w * xx.w;
            }
        }
        __syncthreads();   // all warps done with buf before next prefetch overwrites
    }

    #pragma unroll
    for (int r = 0; r < 8; r++)
        if (r < m) g_T[(size_t)(gbase + r) * SUBF + j] = acc[r] * wts[r];
}

// ---------------- kernel O: stage 2  O[r][o] = sum_j T[r][j]*V1[s][o][j] ----------
// grid (8 o-tiles, 64 subnets), 128 threads. V1 tile resident, T chunks db cp.async.
// T chunk = 8 rows x 128 floats = 4096 B = 2 cp16 per thread.
#define OP 132
#define SMEM_O_BYTES ((128 * OP + 2 * 8 * SUBF) * 4)

__global__ void __launch_bounds__(128) colak_O(const float* __restrict__ V1) {
    const int s  = blockIdx.y;
    const int ot = blockIdx.x;
    const int n  = g_cnt[s];
    if (n == 0) return;
    const int gbase = g_off[s];

    extern __shared__ float smem[];
    float* Vs = smem;            // [128][OP]
    float* Tb = smem + 128 * OP; // 2 x [8][128]

    const int tid  = threadIdx.x;
    const int w    = tid >> 5;
    const int lane = tid & 31;
    const int o    = w * 32 + lane;   // 0..127

    const float* v1 = V1 + (size_t)s * OUTF * SUBF + (size_t)ot * 128 * SUBF;
    #pragma unroll
    for (int k = 0; k < 32; k++) {
        int idx = k * 128 + tid;
        int orow = idx >> 5, seg = idx & 31;
        cp16(Vs + orow * OP + seg * 4, v1 + (size_t)orow * SUBF + seg * 4);
    }
    // prefetch first T chunk into Tb[0]: 8 rows x 32 segs -> 2 cp16/thread
    #pragma unroll
    for (int k = 0; k < 2; k++) {
        int idx = k * 128 + tid;
        int r = idx >> 5, seg = idx & 31;
        cp16(Tb + r * SUBF + seg * 4, g_T + (size_t)(gbase + r) * SUBF + seg * 4);
    }
    CP_COMMIT();

    const int nchunk = (n + 7) >> 3;
    for (int ci = 0; ci < nchunk; ci++) {
        float* tbuf = Tb + (ci & 1) * 8 * SUBF;
        if (ci + 1 < nchunk) {
            float* dst = Tb + ((ci + 1) & 1) * 8 * SUBF;
            #pragma unroll
            for (int k = 0; k < 2; k++) {
                int idx = k * 128 + tid;
                int r = idx >> 5, seg = idx & 31;
                // rows beyond n read within g_T's +8 row padding (garbage ok, not written)
                cp16(dst + r * SUBF + seg * 4,
                     g_T + (size_t)(gbase + (ci + 1) * 8 + r) * SUBF + seg * 4);
            }
            CP_COMMIT();
            CP_WAIT(1);
        } else {
            CP_WAIT(0);
        }
        __syncthreads();

        float acc[8];
        #pragma unroll
        for (int r = 0; r < 8; r++) acc[r] = 0.f;

        const float* vr = Vs + o * OP;
        #pragma unroll
        for (int j4 = 0; j4 < 32; j4++) {
            float4 v = *(const float4*)(vr + (j4 << 2));
            #pragma unroll
            for (int r = 0; r < 8; r++) {
                float4 t = *(const float4*)(tbuf + r * SUBF + (j4 << 2));  // broadcast
                acc[r] += v.x * t.x + v.y * t.y + v.z * t.z + v.w * t.w;
            }
        }

        const int m = min(8, n - ci * 8);
        #pragma unroll
        for (int r = 0; r < 8; r++)
            if (r < m)
                g_opart[(size_t)(gbase + ci * 8 + r) * OUTF + ot * 128 + o] = acc[r];
        __syncthreads();   // protect tbuf before next prefetch overwrites it
    }
}

// ---------------- kernel 4: reduce 8 partials per batch row -----------------------
__global__ void __launch_bounds__(256) colak_reduce(float* __restrict__ out) {
    __shared__ int mp[KACT];
    const int b = blockIdx.x;
    const int tid = threadIdx.x;
    if (tid < KACT) mp[tid] = g_map[b * KACT + tid];
    __syncthreads();
    const float4* op = (const float4*)g_opart;
    float4 sum = make_float4(0.f, 0.f, 0.f, 0.f);
    #pragma unroll
    for (int k = 0; k < KACT; k++) {
        float4 v = op[(size_t)mp[k] * (OUTF / 4) + tid];
        sum.x += v.x; sum.y += v.y; sum.z += v.z; sum.w += v.w;
    }
    ((float4*)out)[(size_t)b * (OUTF / 4) + tid] = sum;
}

// ---------------- host launcher ----------------------------------------------------
extern "C" void kernel_launch(void* const* d_in, const int* in_sizes, int n_in,
                              void* d_out, int out_size) {
    const float* x  = (const float*)d_in[0];
    const float* q  = (const float*)d_in[1];
    const float* Wk = (const float*)d_in[2];
    const float* bk = (const float*)d_in[3];
    const float* V0 = (const float*)d_in[4];
    const float* V1 = (const float*)d_in[5];
    float* out = (float*)d_out;

    cudaFuncSetAttribute(colak_T, cudaFuncAttributeMaxDynamicSharedMemorySize, SMEM_T_BYTES);
    cudaFuncSetAttribute(colak_O, cudaFuncAttributeMaxDynamicSharedMemorySize, SMEM_O_BYTES);

    colak_attn<<<NB / 8, 256>>>(q, Wk, bk);
    colak_scatter<<<1, 256>>>();
    colak_T<<<T_GRID, 128, SMEM_T_BYTES>>>(x, V0);
    colak_O<<<dim3(8, NS), 128, SMEM_O_BYTES>>>(V1);
    colak_reduce<<<NB, 256>>>(out);
}

// round 5
// speedup vs baseline: 1.0023x; 1.0023x over previous
#include <cuda_runtime.h>

#define NB    256
#define NS    64
#define KACT  8
#define INF_  1024
#define OUTF  1024
#define SUBF  128
#define QF    1024
#define NASG  (NB * KACT)      // 2048 total assignments (always exact)
#define KQ    4                // k-split of T across CTAs
#define MAXITEMS 128           // sum ceil(n_s/32) <= 64 + 64

// ---------------- device scratch (static globals: no runtime allocation) ----------
__device__ int   g_cnt[NS];
__device__ int   g_off[NS];
__device__ int   g_sel_s[NASG];
__device__ float g_sel_w[NASG];
__device__ int   g_asg_b[NASG];               // compacted: batch row per assignment
__device__ float g_asg_w[NASG];               // compacted: softmax weight per assignment
__device__ int   g_map[NASG];                 // (b,slot) -> compact index
__device__ int   g_work[MAXITEMS];            // (subnet<<8)|chunk
__device__ int   g_nwork;
__device__ float g_Tpart[KQ * NASG * SUBF];   // stage-1 k-partials (raw sums)
__device__ float g_T[(NASG + 32) * SUBF];     // reduced, weight-applied (+32 row pad, zeros)
__device__ float g_opart[NASG * OUTF];        // 8 MB partial outputs

// ---------------- cp.async helpers ------------------------------------------------
__device__ __forceinline__ void cp16(void* s, const void* g) {
    unsigned sa = (unsigned)__cvta_generic_to_shared(s);
    asm volatile("cp.async.cg.shared.global [%0], [%1], 16;\n" :: "r"(sa), "l"(g));
}
#define CP_COMMIT()  asm volatile("cp.async.commit_group;\n")
#define CP_WAIT(n)   asm volatile("cp.async.wait_group %0;\n" :: "n"(n))

// ---------------- kernel 1: attention + top-8 + softmax ---------------------------
__global__ void __launch_bounds__(256) colak_attn(const float* __restrict__ q,
                                                  const float* __restrict__ Wk,
                                                  const float* __restrict__ bk) {
    __shared__ float qs[8 * QF];
    __shared__ float att[8][NS];
    const int b0   = blockIdx.x * 8;
    const int tid  = threadIdx.x;
    const int w    = tid >> 5;
    const int lane = tid & 31;

    for (int f = tid; f < 8 * (QF / 4); f += 256)
        ((float4*)qs)[f] = ((const float4*)(q + (size_t)b0 * QF))[f];
    __syncthreads();

    const float4* q4 = (const float4*)qs;
    #pragma unroll
    for (int p = 0; p < 8; p++) {
        const int s = p * 8 + w;
        const float4* wr = (const float4*)(Wk + (size_t)s * QF);
        float acc[8];
        #pragma unroll
        for (int r = 0; r < 8; r++) acc[r] = 0.f;
        #pragma unroll
        for (int i = lane; i < QF / 4; i += 32) {
            float4 a = wr[i];
            #pragma unroll
            for (int r = 0; r < 8; r++) {
                float4 c = q4[r * (QF / 4) + i];
                acc[r] += a.x * c.x + a.y * c.y + a.z * c.z + a.w * c.w;
            }
        }
        #pragma unroll
        for (int r = 0; r < 8; r++) {
            float v = acc[r];
            #pragma unroll
            for (int o = 16; o; o >>= 1) v += __shfl_xor_sync(0xffffffffu, v, o);
            if (lane == 0) att[r][s] = v + bk[s];
        }
    }
    __syncthreads();

    if (w < 8) {
        const int b = b0 + w;
        float v0 = att[w][lane], v1 = att[w][lane + 32];
        int r0 = 0, r1 = 0;
        #pragma unroll
        for (int j = 0; j < NS; j++) {
            float a = att[w][j];
            r0 += (a > v0) || (a == v0 && j < lane);
            r1 += (a > v1) || (a == v1 && j < lane + 32);
        }
        bool k0 = r0 < KACT, k1 = r1 < KACT;

        float m = fmaxf(k0 ? v0 : -1e30f, k1 ? v1 : -1e30f);
        #pragma unroll
        for (int o = 16; o; o >>= 1) m = fmaxf(m, __shfl_xor_sync(0xffffffffu, m, o));

        float e0 = k0 ? expf(v0 - m) : 0.f;
        float e1 = k1 ? expf(v1 - m) : 0.f;
        float sm = e0 + e1;
        #pragma unroll
        for (int o = 16; o; o >>= 1) sm += __shfl_xor_sync(0xffffffffu, sm, o);

        unsigned m0 = __ballot_sync(0xffffffffu, k0);
        unsigned m1 = __ballot_sync(0xffffffffu, k1);
        unsigned lt = (1u << lane) - 1u;
        int base1 = __popc(m0);
        if (k0) {
            int slot = __popc(m0 & lt);
            g_sel_s[b * KACT + slot] = lane;
            g_sel_w[b * KACT + slot] = e0 / sm;
        }
        if (k1) {
            int slot = base1 + __popc(m1 & lt);
            g_sel_s[b * KACT + slot] = lane + 32;
            g_sel_w[b * KACT + slot] = e1 / sm;
        }
    }
}

// ---------------- kernel 2: count + scans + compact + work list (one block) -------
__global__ void __launch_bounds__(256) colak_scatter() {
    __shared__ int cnt[NS], off_s[NS], fill[NS], ncoff[NS];
    const int tid = threadIdx.x;
    if (tid < NS) cnt[tid] = 0;
    __syncthreads();
    for (int idx = tid; idx < NASG; idx += 256)
        atomicAdd(&cnt[g_sel_s[idx]], 1);
    __syncthreads();

    if (tid < 32) {
        const int lane = tid;
        int a = cnt[lane], b = cnt[lane + 32];
        int ia = a, ib = b;
        #pragma unroll
        for (int d = 1; d < 32; d <<= 1) {
            int t = __shfl_up_sync(0xffffffffu, ia, d); if (lane >= d) ia += t;
        }
        int tota = __shfl_sync(0xffffffffu, ia, 31);
        #pragma unroll
        for (int d = 1; d < 32; d <<= 1) {
            int t = __shfl_up_sync(0xffffffffu, ib, d); if (lane >= d) ib += t;
        }
        off_s[lane]      = ia - a;
        off_s[lane + 32] = tota + ib - b;

        int nca = (a + 31) >> 5, ncb = (b + 31) >> 5;
        int inca = nca, incb = ncb;
        #pragma unroll
        for (int d = 1; d < 32; d <<= 1) {
            int t = __shfl_up_sync(0xffffffffu, inca, d); if (lane >= d) inca += t;
        }
        int totnca = __shfl_sync(0xffffffffu, inca, 31);
        #pragma unroll
        for (int d = 1; d < 32; d <<= 1) {
            int t = __shfl_up_sync(0xffffffffu, incb, d); if (lane >= d) incb += t;
        }
        ncoff[lane]      = inca - nca;
        ncoff[lane + 32] = totnca + incb - ncb;
        if (lane == 31) g_nwork = totnca + incb;
    }
    __syncthreads();

    if (tid < NS) {
        g_cnt[tid] = cnt[tid]; g_off[tid] = off_s[tid]; fill[tid] = off_s[tid];
        int base = ncoff[tid];
        int nc = (cnt[tid] + 31) >> 5;
        for (int c = 0; c < nc; c++) g_work[base + c] = (tid << 8) | c;
    }
    __syncthreads();
    for (int idx = tid; idx < NASG; idx += 256) {
        int s = g_sel_s[idx];
        int p = atomicAdd(&fill[s], 1);
        g_asg_b[p] = idx >> 3;
        g_asg_w[p] = g_sel_w[idx];
        g_map[idx] = p;
    }
}

// ---------------- kernel T: stage 1 (k-quarter per CTA) ---------------------------
// CTA = (work item = 32 asg rows of one subnet, k-quarter of 256 i).
// 128 threads: warp w owns rows 8w..8w+7; thread owns 8r x 4j (j = 4*lane+c).
// smem: V0 tile [128j][64i] swizzled, double-buffered (64KB) + X [32r][64i] db (16KB).
#define V0TILE (128 * 64)
#define XTILE  (32 * 64)
#define SMEM_T_BYTES ((2 * V0TILE + 2 * XTILE) * 4)

__global__ void __launch_bounds__(128) colak_T(const float* __restrict__ x,
                                               const float* __restrict__ V0) {
    if ((int)blockIdx.x >= g_nwork) return;
    const int item = g_work[blockIdx.x];
    const int s  = item >> 8;
    const int c  = item & 255;
    const int kq = blockIdx.y;            // 0..3
    const int n  = g_cnt[s];
    const int m  = min(32, n - c * 32);
    const int gbase = g_off[s] + c * 32;

    extern __shared__ float smem[];
    float* V0s = smem;                    // 2 x [128][64]
    float* Xs  = smem + 2 * V0TILE;       // 2 x [32][64]
    __shared__ int rows[32];

    const int tid  = threadIdx.x;
    const int w    = tid >> 5;
    const int lane = tid & 31;
    const int r0   = w * 8;
    const int swz  = lane & 7;

    if (tid < 32) rows[tid] = g_asg_b[gbase + min(tid, m - 1)];
    __syncthreads();

    const float* v0 = V0 + (size_t)s * SUBF * INF_;
    const int ibase = kq * 256;

    // staging lambdas (manually inlined): V0 16 cp16/thread, X 4 cp16/thread
    {   // tile 0
        const int i0 = ibase;
        float* vd = V0s; float* xd = Xs;
        #pragma unroll
        for (int k = 0; k < 16; k++) {
            int idx = k * 128 + tid;
            int j = idx >> 4, seg = idx & 15;
            cp16(vd + j * 64 + ((seg ^ ((j >> 2) & 7)) << 2),
                 v0 + (size_t)j * INF_ + i0 + seg * 4);
        }
        #pragma unroll
        for (int k = 0; k < 4; k++) {
            int idx = k * 128 + tid;
            int r = idx >> 4, seg = idx & 15;
            cp16(xd + r * 64 + seg * 4, x + (size_t)rows[r] * INF_ + i0 + seg * 4);
        }
        CP_COMMIT();
    }

    float acc[8][4];
    #pragma unroll
    for (int r = 0; r < 8; r++)
        #pragma unroll
        for (int cc = 0; cc < 4; cc++) acc[r][cc] = 0.f;

    for (int t = 0; t < 4; t++) {
        const float* Vb = V0s + (t & 1) * V0TILE;
        const float* Xb = Xs  + (t & 1) * XTILE;
        if (t + 1 < 4) {
            const int i0 = ibase + (t + 1) * 64;
            float* vd = V0s + ((t + 1) & 1) * V0TILE;
            float* xd = Xs  + ((t + 1) & 1) * XTILE;
            #pragma unroll
            for (int k = 0; k < 16; k++) {
                int idx = k * 128 + tid;
                int j = idx >> 4, seg = idx & 15;
                cp16(vd + j * 64 + ((seg ^ ((j >> 2) & 7)) << 2),
                     v0 + (size_t)j * INF_ + i0 + seg * 4);
            }
            #pragma unroll
            for (int k = 0; k < 4; k++) {
                int idx = k * 128 + tid;
                int r = idx >> 4, seg = idx & 15;
                cp16(xd + r * 64 + seg * 4, x + (size_t)rows[r] * INF_ + i0 + seg * 4);
            }
            CP_COMMIT();
            CP_WAIT(1);
        } else {
            CP_WAIT(0);
        }
        __syncthreads();

        #pragma unroll
        for (int i4 = 0; i4 < 16; i4++) {
            float4 xv[8];
            #pragma unroll
            for (int r = 0; r < 8; r++)
                xv[r] = *(const float4*)(Xb + (r0 + r) * 64 + i4 * 4);
            const int i4s = (i4 ^ swz) << 2;
            #pragma unroll
            for (int cc = 0; cc < 4; cc++) {
                float4 v = *(const float4*)(Vb + (4 * lane + cc) * 64 + i4s);
                #pragma unroll
                for (int r = 0; r < 8; r++)
                    acc[r][cc] += v.x * xv[r].x + v.y * xv[r].y
                                + v.z * xv[r].z + v.w * xv[r].w;
            }
        }
        __syncthreads();
    }

    float* dst = g_Tpart + (size_t)kq * NASG * SUBF;
    #pragma unroll
    for (int r = 0; r < 8; r++) {
        if (r0 + r < m) {
            float4 o = make_float4(acc[r][0], acc[r][1], acc[r][2], acc[r][3]);
            *(float4*)(dst + (size_t)(gbase + r0 + r) * SUBF + 4 * lane) = o;
        }
    }
}

// ---------------- kernel Tred: sum 4 k-partials, apply weight ---------------------
__global__ void __launch_bounds__(256) colak_Tred() {
    const int idx = blockIdx.x * 256 + threadIdx.x;   // 0..65535
    const int row = idx >> 5, qd = idx & 31;
    float4 a = *(const float4*)(g_Tpart + (size_t)row * SUBF + qd * 4);
    #pragma unroll
    for (int h = 1; h < KQ; h++) {
        float4 b = *(const float4*)(g_Tpart + ((size_t)h * NASG + row) * SUBF + qd * 4);
        a.x += b.x; a.y += b.y; a.z += b.z; a.w += b.w;
    }
    const float wt = g_asg_w[row];
    a.x *= wt; a.y *= wt; a.z *= wt; a.w *= wt;
    *(float4*)(g_T + (size_t)row * SUBF + qd * 4) = a;
}

// ---------------- kernel O: stage 2 -----------------------------------------------
// grid (8 o-tiles, 64 subnets), 128 threads. V1 tile [128o][128j] swizzled resident;
// T chunks of 32 rows double-buffered. Warp w owns rows 8w..8w+7; thread 8r x 4o.
#define V1TILE (128 * 128)
#define TSTILE (32 * 128)
#define SMEM_O_BYTES ((V1TILE + 2 * TSTILE) * 4)

__global__ void __launch_bounds__(128) colak_O(const float* __restrict__ V1) {
    const int s  = blockIdx.y;
    const int ot = blockIdx.x;
    const int n  = g_cnt[s];
    if (n == 0) return;
    const int gbase = g_off[s];

    extern __shared__ float smem[];
    float* V1s = smem;                 // [128][128] swizzled
    float* Ts  = smem + V1TILE;        // 2 x [32][128]

    const int tid  = threadIdx.x;
    const int w    = tid >> 5;
    const int lane = tid & 31;
    const int r0   = w * 8;
    const int swz  = lane & 7;

    const float* v1 = V1 + (size_t)s * OUTF * SUBF + (size_t)ot * 128 * SUBF;
    #pragma unroll
    for (int k = 0; k < 32; k++) {
        int idx = k * 128 + tid;
        int o = idx >> 5, seg = idx & 31;
        cp16(V1s + o * 128 + ((seg ^ ((o >> 2) & 7)) << 2),
             v1 + (size_t)o * SUBF + seg * 4);
    }
    #pragma unroll
    for (int k = 0; k < 8; k++) {      // T chunk 0: 32 rows x 32 segs
        int idx = k * 128 + tid;
        int r = idx >> 5, seg = idx & 31;
        cp16(Ts + r * SUBF + seg * 4, g_T + (size_t)(gbase + r) * SUBF + seg * 4);
    }
    CP_COMMIT();

    const int nchunk = (n + 31) >> 5;
    for (int ci = 0; ci < nchunk; ci++) {
        const float* Tb = Ts + (ci & 1) * TSTILE;
        if (ci + 1 < nchunk) {
            float* dst = Ts + ((ci + 1) & 1) * TSTILE;
            #pragma unroll
            for (int k = 0; k < 8; k++) {
                int idx = k * 128 + tid;
                int r = idx >> 5, seg = idx & 31;
                cp16(dst + r * SUBF + seg * 4,
                     g_T + (size_t)(gbase + (ci + 1) * 32 + r) * SUBF + seg * 4);
            }
            CP_COMMIT();
            CP_WAIT(1);
        } else {
            CP_WAIT(0);
        }
        __syncthreads();

        float acc[8][4];
        #pragma unroll
        for (int r = 0; r < 8; r++)
            #pragma unroll
            for (int cc = 0; cc < 4; cc++) acc[r][cc] = 0.f;

        #pragma unroll
        for (int j4 = 0; j4 < 32; j4++) {
            float4 tv[8];
            #pragma unroll
            for (int r = 0; r < 8; r++)
                tv[r] = *(const float4*)(Tb + (r0 + r) * SUBF + j4 * 4);
            const int j4s = (j4 ^ swz) << 2;
            #pragma unroll
            for (int cc = 0; cc < 4; cc++) {
                float4 v = *(const float4*)(V1s + (4 * lane + cc) * 128 + j4s);
                #pragma unroll
                for (int r = 0; r < 8; r++)
                    acc[r][cc] += v.x * tv[r].x + v.y * tv[r].y
                                + v.z * tv[r].z + v.w * tv[r].w;
            }
        }

        const int m = min(32, n - ci * 32);
        #pragma unroll
        for (int r = 0; r < 8; r++) {
            if (r0 + r < m) {
                float4 o = make_float4(acc[r][0], acc[r][1], acc[r][2], acc[r][3]);
                *(float4*)(g_opart + (size_t)(gbase + ci * 32 + r0 + r) * OUTF
                           + ot * 128 + 4 * lane) = o;
            }
        }
        __syncthreads();
    }
}

// ---------------- kernel 4: reduce 8 partials per batch row -----------------------
__global__ void __launch_bounds__(256) colak_reduce(float* __restrict__ out) {
    __shared__ int mp[KACT];
    const int b = blockIdx.x;
    const int tid = threadIdx.x;
    if (tid < KACT) mp[tid] = g_map[b * KACT + tid];
    __syncthreads();
    const float4* op = (const float4*)g_opart;
    float4 sum = make_float4(0.f, 0.f, 0.f, 0.f);
    #pragma unroll
    for (int k = 0; k < KACT; k++) {
        float4 v = op[(size_t)mp[k] * (OUTF / 4) + tid];
        sum.x += v.x; sum.y += v.y; sum.z += v.z; sum.w += v.w;
    }
    ((float4*)out)[(size_t)b * (OUTF / 4) + tid] = sum;
}

// ---------------- host launcher ----------------------------------------------------
extern "C" void kernel_launch(void* const* d_in, const int* in_sizes, int n_in,
                              void* d_out, int out_size) {
    const float* x  = (const float*)d_in[0];
    const float* q  = (const float*)d_in[1];
    const float* Wk = (const float*)d_in[2];
    const float* bk = (const float*)d_in[3];
    const float* V0 = (const float*)d_in[4];
    const float* V1 = (const float*)d_in[5];
    float* out = (float*)d_out;

    cudaFuncSetAttribute(colak_T, cudaFuncAttributeMaxDynamicSharedMemorySize, SMEM_T_BYTES);
    cudaFuncSetAttribute(colak_O, cudaFuncAttributeMaxDynamicSharedMemorySize, SMEM_O_BYTES);

    colak_attn<<<NB / 8, 256>>>(q, Wk, bk);
    colak_scatter<<<1, 256>>>();
    colak_T<<<dim3(MAXITEMS, KQ), 128, SMEM_T_BYTES>>>(x, V0);
    colak_Tred<<<NASG * SUBF / (256 * 4), 256>>>();
    colak_O<<<dim3(8, NS), 128, SMEM_O_BYTES>>>(V1);
    colak_reduce<<<NB, 256>>>(out);
}

// round 6
// speedup vs baseline: 1.3093x; 1.3064x over previous
#include <cuda_runtime.h>

#define NB    256
#define NS    64
#define KACT  8
#define INF_  1024
#define OUTF  1024
#define SUBF  128
#define QF    1024
#define NASG  (NB * KACT)      // 2048 total assignments (always exact)
#define KQ    4                // k-split of T across CTAs
#define MAXITEMS 128           // sum ceil(n_s/32) <= 128

// ---------------- device scratch (static globals: no runtime allocation) ----------
__device__ int   g_cnt[NS];
__device__ int   g_off[NS];
__device__ int   g_sel_s[NASG];
__device__ float g_sel_w[NASG];
__device__ int   g_asg_b[NASG];               // compacted: batch row per assignment
__device__ float g_asg_w[NASG];               // compacted: softmax weight per assignment
__device__ int   g_map[NASG];                 // (b,slot) -> compact index
__device__ int   g_work[MAXITEMS];            // (subnet<<8)|chunk
__device__ int   g_nwork;
__device__ float g_Tpart[KQ * NASG * SUBF];   // stage-1 k-partials (raw sums)
__device__ float g_T[(NASG + 32) * SUBF];     // reduced, weight-applied (+32 row pad)
__device__ float g_opart[NASG * OUTF];        // 8 MB partial outputs

// ---------------- cp.async helpers ------------------------------------------------
__device__ __forceinline__ void cp16(void* s, const void* g) {
    unsigned sa = (unsigned)__cvta_generic_to_shared(s);
    asm volatile("cp.async.cg.shared.global [%0], [%1], 16;\n" :: "r"(sa), "l"(g));
}
#define CP_COMMIT()  asm volatile("cp.async.commit_group;\n")
#define CP_WAIT(n)   asm volatile("cp.async.wait_group %0;\n" :: "n"(n))

// ---------------- kernel 1: attention + top-8 + softmax ---------------------------
__global__ void __launch_bounds__(256) colak_attn(const float* __restrict__ q,
                                                  const float* __restrict__ Wk,
                                                  const float* __restrict__ bk) {
    __shared__ float qs[8 * QF];
    __shared__ float att[8][NS];
    const int b0   = blockIdx.x * 8;
    const int tid  = threadIdx.x;
    const int w    = tid >> 5;
    const int lane = tid & 31;

    for (int f = tid; f < 8 * (QF / 4); f += 256)
        ((float4*)qs)[f] = ((const float4*)(q + (size_t)b0 * QF))[f];
    __syncthreads();

    const float4* q4 = (const float4*)qs;
    #pragma unroll
    for (int p = 0; p < 8; p++) {
        const int s = p * 8 + w;
        const float4* wr = (const float4*)(Wk + (size_t)s * QF);
        float acc[8];
        #pragma unroll
        for (int r = 0; r < 8; r++) acc[r] = 0.f;
        #pragma unroll
        for (int i = lane; i < QF / 4; i += 32) {
            float4 a = wr[i];
            #pragma unroll
            for (int r = 0; r < 8; r++) {
                float4 c = q4[r * (QF / 4) + i];
                acc[r] += a.x * c.x + a.y * c.y + a.z * c.z + a.w * c.w;
            }
        }
        #pragma unroll
        for (int r = 0; r < 8; r++) {
            float v = acc[r];
            #pragma unroll
            for (int o = 16; o; o >>= 1) v += __shfl_xor_sync(0xffffffffu, v, o);
            if (lane == 0) att[r][s] = v + bk[s];
        }
    }
    __syncthreads();

    if (w < 8) {
        const int b = b0 + w;
        float v0 = att[w][lane], v1 = att[w][lane + 32];
        int r0 = 0, r1 = 0;
        #pragma unroll
        for (int j = 0; j < NS; j++) {
            float a = att[w][j];
            r0 += (a > v0) || (a == v0 && j < lane);
            r1 += (a > v1) || (a == v1 && j < lane + 32);
        }
        bool k0 = r0 < KACT, k1 = r1 < KACT;

        float m = fmaxf(k0 ? v0 : -1e30f, k1 ? v1 : -1e30f);
        #pragma unroll
        for (int o = 16; o; o >>= 1) m = fmaxf(m, __shfl_xor_sync(0xffffffffu, m, o));

        float e0 = k0 ? expf(v0 - m) : 0.f;
        float e1 = k1 ? expf(v1 - m) : 0.f;
        float sm = e0 + e1;
        #pragma unroll
        for (int o = 16; o; o >>= 1) sm += __shfl_xor_sync(0xffffffffu, sm, o);

        unsigned m0 = __ballot_sync(0xffffffffu, k0);
        unsigned m1 = __ballot_sync(0xffffffffu, k1);
        unsigned lt = (1u << lane) - 1u;
        int base1 = __popc(m0);
        if (k0) {
            int slot = __popc(m0 & lt);
            g_sel_s[b * KACT + slot] = lane;
            g_sel_w[b * KACT + slot] = e0 / sm;
        }
        if (k1) {
            int slot = base1 + __popc(m1 & lt);
            g_sel_s[b * KACT + slot] = lane + 32;
            g_sel_w[b * KACT + slot] = e1 / sm;
        }
    }
}

// ---------------- kernel 2: count + scans + compact + work list (one block) -------
__global__ void __launch_bounds__(256) colak_scatter() {
    __shared__ int cnt[NS], off_s[NS], fill[NS], ncoff[NS];
    const int tid = threadIdx.x;
    if (tid < NS) cnt[tid] = 0;
    __syncthreads();
    for (int idx = tid; idx < NASG; idx += 256)
        atomicAdd(&cnt[g_sel_s[idx]], 1);
    __syncthreads();

    if (tid < 32) {
        const int lane = tid;
        int a = cnt[lane], b = cnt[lane + 32];
        int ia = a, ib = b;
        #pragma unroll
        for (int d = 1; d < 32; d <<= 1) {
            int t = __shfl_up_sync(0xffffffffu, ia, d); if (lane >= d) ia += t;
        }
        int tota = __shfl_sync(0xffffffffu, ia, 31);
        #pragma unroll
        for (int d = 1; d < 32; d <<= 1) {
            int t = __shfl_up_sync(0xffffffffu, ib, d); if (lane >= d) ib += t;
        }
        off_s[lane]      = ia - a;
        off_s[lane + 32] = tota + ib - b;

        int nca = (a + 31) >> 5, ncb = (b + 31) >> 5;
        int inca = nca, incb = ncb;
        #pragma unroll
        for (int d = 1; d < 32; d <<= 1) {
            int t = __shfl_up_sync(0xffffffffu, inca, d); if (lane >= d) inca += t;
        }
        int totnca = __shfl_sync(0xffffffffu, inca, 31);
        #pragma unroll
        for (int d = 1; d < 32; d <<= 1) {
            int t = __shfl_up_sync(0xffffffffu, incb, d); if (lane >= d) incb += t;
        }
        ncoff[lane]      = inca - nca;
        ncoff[lane + 32] = totnca + incb - ncb;
        if (lane == 31) g_nwork = totnca + incb;
    }
    __syncthreads();

    if (tid < NS) {
        g_cnt[tid] = cnt[tid]; g_off[tid] = off_s[tid]; fill[tid] = off_s[tid];
        int base = ncoff[tid];
        int nc = (cnt[tid] + 31) >> 5;
        for (int c = 0; c < nc; c++) g_work[base + c] = (tid << 8) | c;
    }
    __syncthreads();
    for (int idx = tid; idx < NASG; idx += 256) {
        int s = g_sel_s[idx];
        int p = atomicAdd(&fill[s], 1);
        g_asg_b[p] = idx >> 3;
        g_asg_w[p] = g_sel_w[idx];
        g_map[idx] = p;
    }
}

// ---------------- kernel T: stage 1 (k-quarter per CTA) ---------------------------
// CTA = (32 asg rows of one subnet, k-quarter of 256 i). 256 threads, 8 warps.
// Warp w owns rows 4w..4w+3; thread owns 4r x 4j (j = 4*lane+cc). 16 acc regs.
// smem: V0 tile [128j][32i] swizzled db (32KB) + X [32r][32i] db (8KB) = 40KB.
#define V0TILE (128 * 32)
#define XTILE  (32 * 32)
#define SMEM_T_BYTES ((2 * V0TILE + 2 * XTILE) * 4)

__global__ void __launch_bounds__(256, 3) colak_T(const float* __restrict__ x,
                                                  const float* __restrict__ V0) {
    if ((int)blockIdx.x >= g_nwork) return;
    const int item = g_work[blockIdx.x];
    const int s  = item >> 8;
    const int c  = item & 255;
    const int kq = blockIdx.y;            // 0..3
    const int n  = g_cnt[s];
    const int m  = min(32, n - c * 32);
    const int gbase = g_off[s] + c * 32;

    extern __shared__ float smem[];
    float* V0s = smem;                    // 2 x [128][32]
    float* Xs  = smem + 2 * V0TILE;       // 2 x [32][32]
    __shared__ int rows[32];

    const int tid  = threadIdx.x;
    const int w    = tid >> 5;
    const int lane = tid & 31;
    const int r0   = w * 4;
    const int swz  = lane & 7;

    if (tid < 32) rows[tid] = g_asg_b[gbase + min(tid, m - 1)];
    __syncthreads();

    const float* v0 = V0 + (size_t)s * SUBF * INF_;
    const int ibase = kq * 256;
    const int vj_ = tid >> 3;             // V0 staging: thread -> (row base, seg)
    const int vs_ = tid & 7;
    const float* xrow = x + (size_t)rows[vj_ & 31] * INF_;   // X staging row (tid>>3 dup ok)

    // prefetch tile 0
    {
        float* vd = V0s; float* xd = Xs;
        #pragma unroll
        for (int k = 0; k < 4; k++) {
            int j = k * 32 + vj_;
            cp16(vd + j * 32 + ((vs_ ^ ((j >> 2) & 7)) << 2),
                 v0 + (size_t)j * INF_ + ibase + vs_ * 4);
        }
        cp16(xd + (tid >> 3) * 32 + vs_ * 4, xrow + ibase + vs_ * 4);
        CP_COMMIT();
    }

    float acc[4][4];
    #pragma unroll
    for (int r = 0; r < 4; r++)
        #pragma unroll
        for (int cc = 0; cc < 4; cc++) acc[r][cc] = 0.f;

    for (int t = 0; t < 8; t++) {
        const float* Vb = V0s + (t & 1) * V0TILE;
        const float* Xb = Xs  + (t & 1) * XTILE;
        if (t + 1 < 8) {
            const int i0 = ibase + (t + 1) * 32;
            float* vd = V0s + ((t + 1) & 1) * V0TILE;
            float* xd = Xs  + ((t + 1) & 1) * XTILE;
            #pragma unroll
            for (int k = 0; k < 4; k++) {
                int j = k * 32 + vj_;
                cp16(vd + j * 32 + ((vs_ ^ ((j >> 2) & 7)) << 2),
                     v0 + (size_t)j * INF_ + i0 + vs_ * 4);
            }
            cp16(xd + (tid >> 3) * 32 + vs_ * 4, xrow + i0 + vs_ * 4);
            CP_COMMIT();
            CP_WAIT(1);
        } else {
            CP_WAIT(0);
        }
        __syncthreads();

        #pragma unroll
        for (int i4 = 0; i4 < 8; i4++) {
            float4 xv[4];
            #pragma unroll
            for (int r = 0; r < 4; r++)
                xv[r] = *(const float4*)(Xb + (r0 + r) * 32 + i4 * 4);   // broadcast
            const int i4s = (i4 ^ swz) << 2;
            #pragma unroll
            for (int cc = 0; cc < 4; cc++) {
                float4 v = *(const float4*)(Vb + (4 * lane + cc) * 32 + i4s);
                #pragma unroll
                for (int r = 0; r < 4; r++)
                    acc[r][cc] += v.x * xv[r].x + v.y * xv[r].y
                                + v.z * xv[r].z + v.w * xv[r].w;
            }
        }
        __syncthreads();   // all warps done with buf before next prefetch overwrites
    }

    float* dst = g_Tpart + (size_t)kq * NASG * SUBF;
    #pragma unroll
    for (int r = 0; r < 4; r++) {
        if (r0 + r < m) {
            float4 o = make_float4(acc[r][0], acc[r][1], acc[r][2], acc[r][3]);
            *(float4*)(dst + (size_t)(gbase + r0 + r) * SUBF + 4 * lane) = o;
        }
    }
}

// ---------------- kernel Tred: sum 4 k-partials, apply weight ---------------------
__global__ void __launch_bounds__(256) colak_Tred() {
    const int idx = blockIdx.x * 256 + threadIdx.x;   // 0..65535
    const int row = idx >> 5, qd = idx & 31;
    float4 a = *(const float4*)(g_Tpart + (size_t)row * SUBF + qd * 4);
    #pragma unroll
    for (int h = 1; h < KQ; h++) {
        float4 b = *(const float4*)(g_Tpart + ((size_t)h * NASG + row) * SUBF + qd * 4);
        a.x += b.x; a.y += b.y; a.z += b.z; a.w += b.w;
    }
    const float wt = g_asg_w[row];
    a.x *= wt; a.y *= wt; a.z *= wt; a.w *= wt;
    *(float4*)(g_T + (size_t)row * SUBF + qd * 4) = a;
}

// ---------------- kernel O: stage 2  O[r][o] = sum_j T[r][j]*V1[s][o][j] ----------
// CTA = (32 asg rows, 128-wide o-tile). 256 threads. k-tiles of 32 j, db cp.async.
// smem: V1 tile [128o][32j] swizzled db (32KB) + T [32r][32j] db (8KB) = 40KB.
#define V1TILE (128 * 32)
#define TTILE  (32 * 32)
#define SMEM_O_BYTES ((2 * V1TILE + 2 * TTILE) * 4)

__global__ void __launch_bounds__(256, 3) colak_O(const float* __restrict__ V1) {
    if ((int)blockIdx.x >= g_nwork) return;
    const int item = g_work[blockIdx.x];
    const int s  = item >> 8;
    const int c  = item & 255;
    const int ot = blockIdx.y;            // 0..7
    const int n  = g_cnt[s];
    const int m  = min(32, n - c * 32);
    const int gbase = g_off[s] + c * 32;

    extern __shared__ float smem[];
    float* V1s = smem;                    // 2 x [128][32]
    float* Ts  = smem + 2 * V1TILE;       // 2 x [32][32]

    const int tid  = threadIdx.x;
    const int w    = tid >> 5;
    const int lane = tid & 31;
    const int r0   = w * 4;
    const int swz  = lane & 7;

    const float* v1 = V1 + (size_t)s * OUTF * SUBF + (size_t)ot * 128 * SUBF;
    const float* tsrc = g_T + (size_t)gbase * SUBF;
    const int vj_ = tid >> 3;
    const int vs_ = tid & 7;

    // prefetch tile 0 (j0 = 0)
    {
        #pragma unroll
        for (int k = 0; k < 4; k++) {
            int o = k * 32 + vj_;
            cp16(V1s + o * 32 + ((vs_ ^ ((o >> 2) & 7)) << 2),
                 v1 + (size_t)o * SUBF + vs_ * 4);
        }
        cp16(Ts + (tid >> 3) * 32 + vs_ * 4, tsrc + (size_t)(tid >> 3) * SUBF + vs_ * 4);
        CP_COMMIT();
    }

    float acc[4][4];
    #pragma unroll
    for (int r = 0; r < 4; r++)
        #pragma unroll
        for (int cc = 0; cc < 4; cc++) acc[r][cc] = 0.f;

    for (int t = 0; t < 4; t++) {
        const float* Vb = V1s + (t & 1) * V1TILE;
        const float* Tb = Ts  + (t & 1) * TTILE;
        if (t + 1 < 4) {
            const int j0 = (t + 1) * 32;
            float* vd = V1s + ((t + 1) & 1) * V1TILE;
            float* td = Ts  + ((t + 1) & 1) * TTILE;
            #pragma unroll
            for (int k = 0; k < 4; k++) {
                int o = k * 32 + vj_;
                cp16(vd + o * 32 + ((vs_ ^ ((o >> 2) & 7)) << 2),
                     v1 + (size_t)o * SUBF + j0 + vs_ * 4);
            }
            cp16(td + (tid >> 3) * 32 + vs_ * 4,
                 tsrc + (size_t)(tid >> 3) * SUBF + j0 + vs_ * 4);
            CP_COMMIT();
            CP_WAIT(1);
        } else {
            CP_WAIT(0);
        }
        __syncthreads();

        #pragma unroll
        for (int j4 = 0; j4 < 8; j4++) {
            float4 tv[4];
            #pragma unroll
            for (int r = 0; r < 4; r++)
                tv[r] = *(const float4*)(Tb + (r0 + r) * 32 + j4 * 4);   // broadcast
            const int j4s = (j4 ^ swz) << 2;
            #pragma unroll
            for (int cc = 0; cc < 4; cc++) {
                float4 v = *(const float4*)(Vb + (4 * lane + cc) * 32 + j4s);
                #pragma unroll
                for (int r = 0; r < 4; r++)
                    acc[r][cc] += v.x * tv[r].x + v.y * tv[r].y
                                + v.z * tv[r].z + v.w * tv[r].w;
            }
        }
        __syncthreads();
    }

    #pragma unroll
    for (int r = 0; r < 4; r++) {
        if (r0 + r < m) {
            float4 o = make_float4(acc[r][0], acc[r][1], acc[r][2], acc[r][3]);
            *(float4*)(g_opart + (size_t)(gbase + r0 + r) * OUTF
                       + ot * 128 + 4 * lane) = o;
        }
    }
}

// ---------------- kernel 4: reduce 8 partials per batch row -----------------------
__global__ void __launch_bounds__(256) colak_reduce(float* __restrict__ out) {
    __shared__ int mp[KACT];
    const int b = blockIdx.x;
    const int tid = threadIdx.x;
    if (tid < KACT) mp[tid] = g_map[b * KACT + tid];
    __syncthreads();
    const float4* op = (const float4*)g_opart;
    float4 sum = make_float4(0.f, 0.f, 0.f, 0.f);
    #pragma unroll
    for (int k = 0; k < KACT; k++) {
        float4 v = op[(size_t)mp[k] * (OUTF / 4) + tid];
        sum.x += v.x; sum.y += v.y; sum.z += v.z; sum.w += v.w;
    }
    ((float4*)out)[(size_t)b * (OUTF / 4) + tid] = sum;
}

// ---------------- host launcher ----------------------------------------------------
extern "C" void kernel_launch(void* const* d_in, const int* in_sizes, int n_in,
                              void* d_out, int out_size) {
    const float* x  = (const float*)d_in[0];
    const float* q  = (const float*)d_in[1];
    const float* Wk = (const float*)d_in[2];
    const float* bk = (const float*)d_in[3];
    const float* V0 = (const float*)d_in[4];
    const float* V1 = (const float*)d_in[5];
    float* out = (float*)d_out;

    colak_attn<<<NB / 8, 256>>>(q, Wk, bk);
    colak_scatter<<<1, 256>>>();
    colak_T<<<dim3(MAXITEMS, KQ), 256, SMEM_T_BYTES>>>(x, V0);
    colak_Tred<<<NASG * SUBF / (256 * 4), 256>>>();
    colak_O<<<dim3(MAXITEMS, 8), 256, SMEM_O_BYTES>>>(V1);
    colak_reduce<<<NB, 256>>>(out);
}

// round 7
// speedup vs baseline: 1.5272x; 1.1664x over previous
#include <cuda_runtime.h>

#define NB    256
#define NS    64
#define KACT  8
#define INF_  1024
#define OUTF  1024
#define SUBF  128
#define QF    1024
#define NASG  (NB * KACT)      // 2048 total assignments (always exact)
#define KQ    4                // k-split of T across CTAs
#define RPI   16               // rows per work item
#define MAXITEMS 192           // sum ceil(n_s/16) <= 128 + 64

// ---------------- device scratch (static globals: no runtime allocation) ----------
__device__ int   g_cnt[NS];
__device__ int   g_off[NS];
__device__ int   g_sel_s[NASG];
__device__ float g_sel_w[NASG];
__device__ int   g_asg_b[NASG];               // compacted: batch row per assignment
__device__ float g_asg_w[NASG];               // compacted: softmax weight per assignment
__device__ int   g_map[NASG];                 // (b,slot) -> compact index
__device__ int   g_work[MAXITEMS];            // (subnet<<8)|chunk
__device__ int   g_nwork;
__device__ float g_Tpart[KQ * NASG * SUBF];   // stage-1 k-partials (raw sums)
__device__ float g_T[(NASG + RPI) * SUBF];    // reduced, weight-applied (+pad rows)
__device__ float g_opart[NASG * OUTF];        // 8 MB partial outputs

// ---------------- cp.async helpers ------------------------------------------------
__device__ __forceinline__ void cp16(void* s, const void* g) {
    unsigned sa = (unsigned)__cvta_generic_to_shared(s);
    asm volatile("cp.async.cg.shared.global [%0], [%1], 16;\n" :: "r"(sa), "l"(g));
}
#define CP_COMMIT()  asm volatile("cp.async.commit_group;\n")
#define CP_WAIT(n)   asm volatile("cp.async.wait_group %0;\n" :: "n"(n))

// ---------------- kernel 1: attention + top-8 + softmax ---------------------------
// 64 CTAs x 256 threads, 4 batch rows per CTA.
__global__ void __launch_bounds__(256) colak_attn(const float* __restrict__ q,
                                                  const float* __restrict__ Wk,
                                                  const float* __restrict__ bk) {
    __shared__ float qs[4 * QF];
    __shared__ float att[4][NS];
    const int b0   = blockIdx.x * 4;
    const int tid  = threadIdx.x;
    const int w    = tid >> 5;
    const int lane = tid & 31;

    for (int f = tid; f < 4 * (QF / 4); f += 256)
        ((float4*)qs)[f] = ((const float4*)(q + (size_t)b0 * QF))[f];
    __syncthreads();

    const float4* q4 = (const float4*)qs;
    #pragma unroll
    for (int p = 0; p < 8; p++) {
        const int s = p * 8 + w;
        const float4* wr = (const float4*)(Wk + (size_t)s * QF);
        float acc[4];
        #pragma unroll
        for (int r = 0; r < 4; r++) acc[r] = 0.f;
        #pragma unroll
        for (int i = lane; i < QF / 4; i += 32) {
            float4 a = wr[i];
            #pragma unroll
            for (int r = 0; r < 4; r++) {
                float4 c = q4[r * (QF / 4) + i];
                acc[r] += a.x * c.x + a.y * c.y + a.z * c.z + a.w * c.w;
            }
        }
        #pragma unroll
        for (int r = 0; r < 4; r++) {
            float v = acc[r];
            #pragma unroll
            for (int o = 16; o; o >>= 1) v += __shfl_xor_sync(0xffffffffu, v, o);
            if (lane == 0) att[r][s] = v + bk[s];
        }
    }
    __syncthreads();

    if (w < 4) {
        const int b = b0 + w;
        float v0 = att[w][lane], v1 = att[w][lane + 32];
        int r0 = 0, r1 = 0;
        #pragma unroll
        for (int j = 0; j < NS; j++) {
            float a = att[w][j];
            r0 += (a > v0) || (a == v0 && j < lane);
            r1 += (a > v1) || (a == v1 && j < lane + 32);
        }
        bool k0 = r0 < KACT, k1 = r1 < KACT;

        float m = fmaxf(k0 ? v0 : -1e30f, k1 ? v1 : -1e30f);
        #pragma unroll
        for (int o = 16; o; o >>= 1) m = fmaxf(m, __shfl_xor_sync(0xffffffffu, m, o));

        float e0 = k0 ? expf(v0 - m) : 0.f;
        float e1 = k1 ? expf(v1 - m) : 0.f;
        float sm = e0 + e1;
        #pragma unroll
        for (int o = 16; o; o >>= 1) sm += __shfl_xor_sync(0xffffffffu, sm, o);

        unsigned m0 = __ballot_sync(0xffffffffu, k0);
        unsigned m1 = __ballot_sync(0xffffffffu, k1);
        unsigned lt = (1u << lane) - 1u;
        int base1 = __popc(m0);
        if (k0) {
            int slot = __popc(m0 & lt);
            g_sel_s[b * KACT + slot] = lane;
            g_sel_w[b * KACT + slot] = e0 / sm;
        }
        if (k1) {
            int slot = base1 + __popc(m1 & lt);
            g_sel_s[b * KACT + slot] = lane + 32;
            g_sel_w[b * KACT + slot] = e1 / sm;
        }
    }
}

// ---------------- kernel 2: count + scans + compact + work list (one block) -------
__global__ void __launch_bounds__(256) colak_scatter() {
    __shared__ int cnt[NS], off_s[NS], fill[NS], ncoff[NS];
    const int tid = threadIdx.x;
    if (tid < NS) cnt[tid] = 0;
    __syncthreads();
    for (int idx = tid; idx < NASG; idx += 256)
        atomicAdd(&cnt[g_sel_s[idx]], 1);
    __syncthreads();

    if (tid < 32) {
        const int lane = tid;
        int a = cnt[lane], b = cnt[lane + 32];
        int ia = a, ib = b;
        #pragma unroll
        for (int d = 1; d < 32; d <<= 1) {
            int t = __shfl_up_sync(0xffffffffu, ia, d); if (lane >= d) ia += t;
        }
        int tota = __shfl_sync(0xffffffffu, ia, 31);
        #pragma unroll
        for (int d = 1; d < 32; d <<= 1) {
            int t = __shfl_up_sync(0xffffffffu, ib, d); if (lane >= d) ib += t;
        }
        off_s[lane]      = ia - a;
        off_s[lane + 32] = tota + ib - b;

        int nca = (a + RPI - 1) / RPI, ncb = (b + RPI - 1) / RPI;
        int inca = nca, incb = ncb;
        #pragma unroll
        for (int d = 1; d < 32; d <<= 1) {
            int t = __shfl_up_sync(0xffffffffu, inca, d); if (lane >= d) inca += t;
        }
        int totnca = __shfl_sync(0xffffffffu, inca, 31);
        #pragma unroll
        for (int d = 1; d < 32; d <<= 1) {
            int t = __shfl_up_sync(0xffffffffu, incb, d); if (lane >= d) incb += t;
        }
        ncoff[lane]      = inca - nca;
        ncoff[lane + 32] = totnca + incb - ncb;
        if (lane == 31) g_nwork = totnca + incb;
    }
    __syncthreads();

    if (tid < NS) {
        g_cnt[tid] = cnt[tid]; g_off[tid] = off_s[tid]; fill[tid] = off_s[tid];
        int base = ncoff[tid];
        int nc = (cnt[tid] + RPI - 1) / RPI;
        for (int c = 0; c < nc; c++) g_work[base + c] = (tid << 8) | c;
    }
    __syncthreads();
    for (int idx = tid; idx < NASG; idx += 256) {
        int s = g_sel_s[idx];
        int p = atomicAdd(&fill[s], 1);
        g_asg_b[p] = idx >> 3;
        g_asg_w[p] = g_sel_w[idx];
        g_map[idx] = p;
    }
}

// ---------------- kernel T: stage 1 (k-quarter per CTA) ---------------------------
// CTA = (16 asg rows of one subnet, k-quarter of 256 i). 128 threads, 4 warps.
// Warp w owns rows 4w..4w+3; thread owns 4r x 4j (j = 4*lane+cc). 16 acc regs.
// smem: V0 tile [128j][32i] swizzled db (32KB) + X [16r][32i] db (4KB) = 36KB.
#define V0TILE (128 * 32)
#define XTILE  (RPI * 32)
#define SMEM_T_BYTES ((2 * V0TILE + 2 * XTILE) * 4)

__global__ void __launch_bounds__(128, 6) colak_T(const float* __restrict__ x,
                                                  const float* __restrict__ V0) {
    if ((int)blockIdx.x >= g_nwork) return;
    const int item = g_work[blockIdx.x];
    const int s  = item >> 8;
    const int c  = item & 255;
    const int kq = blockIdx.y;            // 0..3
    const int n  = g_cnt[s];
    const int m  = min(RPI, n - c * RPI);
    const int gbase = g_off[s] + c * RPI;

    extern __shared__ float smem[];
    float* V0s = smem;                    // 2 x [128][32]
    float* Xs  = smem + 2 * V0TILE;       // 2 x [16][32]
    __shared__ int rows[RPI];

    const int tid  = threadIdx.x;
    const int w    = tid >> 5;
    const int lane = tid & 31;
    const int r0   = w * 4;
    const int swz  = lane & 7;

    if (tid < RPI) rows[tid] = g_asg_b[gbase + min(tid, m - 1)];
    __syncthreads();

    const float* v0 = V0 + (size_t)s * SUBF * INF_;
    const int ibase = kq * 256;
    const int xr_ = tid >> 3;             // X staging: row 0..15
    const int vs_ = tid & 7;              // seg 0..7
    const float* xrow = x + (size_t)rows[xr_] * INF_;

    // prefetch tile 0
    {
        #pragma unroll
        for (int k = 0; k < 8; k++) {
            int idx = k * 128 + tid;
            int j = idx >> 3, seg = idx & 7;
            cp16(V0s + j * 32 + ((seg ^ ((j >> 2) & 7)) << 2),
                 v0 + (size_t)j * INF_ + ibase + seg * 4);
        }
        cp16(Xs + xr_ * 32 + vs_ * 4, xrow + ibase + vs_ * 4);
        CP_COMMIT();
    }

    float acc[4][4];
    #pragma unroll
    for (int r = 0; r < 4; r++)
        #pragma unroll
        for (int cc = 0; cc < 4; cc++) acc[r][cc] = 0.f;

    for (int t = 0; t < 8; t++) {
        const float* Vb = V0s + (t & 1) * V0TILE;
        const float* Xb = Xs  + (t & 1) * XTILE;
        if (t + 1 < 8) {
            const int i0 = ibase + (t + 1) * 32;
            float* vd = V0s + ((t + 1) & 1) * V0TILE;
            float* xd = Xs  + ((t + 1) & 1) * XTILE;
            #pragma unroll
            for (int k = 0; k < 8; k++) {
                int idx = k * 128 + tid;
                int j = idx >> 3, seg = idx & 7;
                cp16(vd + j * 32 + ((seg ^ ((j >> 2) & 7)) << 2),
                     v0 + (size_t)j * INF_ + i0 + seg * 4);
            }
            cp16(xd + xr_ * 32 + vs_ * 4, xrow + i0 + vs_ * 4);
            CP_COMMIT();
            CP_WAIT(1);
        } else {
            CP_WAIT(0);
        }
        __syncthreads();

        #pragma unroll
        for (int i4 = 0; i4 < 8; i4++) {
            float4 xv[4];
            #pragma unroll
            for (int r = 0; r < 4; r++)
                xv[r] = *(const float4*)(Xb + (r0 + r) * 32 + i4 * 4);   // broadcast
            const int i4s = (i4 ^ swz) << 2;
            #pragma unroll
            for (int cc = 0; cc < 4; cc++) {
                float4 v = *(const float4*)(Vb + (4 * lane + cc) * 32 + i4s);
                #pragma unroll
                for (int r = 0; r < 4; r++)
                    acc[r][cc] += v.x * xv[r].x + v.y * xv[r].y
                                + v.z * xv[r].z + v.w * xv[r].w;
            }
        }
        __syncthreads();   // all warps done with buf before next prefetch overwrites
    }

    float* dst = g_Tpart + (size_t)kq * NASG * SUBF;
    #pragma unroll
    for (int r = 0; r < 4; r++) {
        if (r0 + r < m) {
            float4 o = make_float4(acc[r][0], acc[r][1], acc[r][2], acc[r][3]);
            *(float4*)(dst + (size_t)(gbase + r0 + r) * SUBF + 4 * lane) = o;
        }
    }
}

// ---------------- kernel Tred: sum 4 k-partials, apply weight ---------------------
__global__ void __launch_bounds__(256) colak_Tred() {
    const int idx = blockIdx.x * 256 + threadIdx.x;   // 0..65535
    const int row = idx >> 5, qd = idx & 31;
    float4 a = *(const float4*)(g_Tpart + (size_t)row * SUBF + qd * 4);
    #pragma unroll
    for (int h = 1; h < KQ; h++) {
        float4 b = *(const float4*)(g_Tpart + ((size_t)h * NASG + row) * SUBF + qd * 4);
        a.x += b.x; a.y += b.y; a.z += b.z; a.w += b.w;
    }
    const float wt = g_asg_w[row];
    a.x *= wt; a.y *= wt; a.z *= wt; a.w *= wt;
    *(float4*)(g_T + (size_t)row * SUBF + qd * 4) = a;
}

// ---------------- kernel O: stage 2  O[r][o] = sum_j T[r][j]*V1[s][o][j] ----------
// CTA = (16 asg rows, 128-wide o-tile). 128 threads. k-tiles of 32 j, db cp.async.
// smem: V1 tile [128o][32j] swizzled db (32KB) + T [16r][32j] db (4KB) = 36KB.
#define V1TILE (128 * 32)
#define TTILE  (RPI * 32)
#define SMEM_O_BYTES ((2 * V1TILE + 2 * TTILE) * 4)

__global__ void __launch_bounds__(128, 6) colak_O(const float* __restrict__ V1) {
    if ((int)blockIdx.x >= g_nwork) return;
    const int item = g_work[blockIdx.x];
    const int s  = item >> 8;
    const int c  = item & 255;
    const int ot = blockIdx.y;            // 0..7
    const int n  = g_cnt[s];
    const int m  = min(RPI, n - c * RPI);
    const int gbase = g_off[s] + c * RPI;

    extern __shared__ float smem[];
    float* V1s = smem;                    // 2 x [128][32]
    float* Ts  = smem + 2 * V1TILE;       // 2 x [16][32]

    const int tid  = threadIdx.x;
    const int w    = tid >> 5;
    const int lane = tid & 31;
    const int r0   = w * 4;
    const int swz  = lane & 7;

    const float* v1 = V1 + (size_t)s * OUTF * SUBF + (size_t)ot * 128 * SUBF;
    const float* tsrc = g_T + (size_t)gbase * SUBF;
    const int xr_ = tid >> 3;
    const int vs_ = tid & 7;

    // prefetch tile 0 (j0 = 0)
    {
        #pragma unroll
        for (int k = 0; k < 8; k++) {
            int idx = k * 128 + tid;
            int o = idx >> 3, seg = idx & 7;
            cp16(V1s + o * 32 + ((seg ^ ((o >> 2) & 7)) << 2),
                 v1 + (size_t)o * SUBF + seg * 4);
        }
        cp16(Ts + xr_ * 32 + vs_ * 4, tsrc + (size_t)xr_ * SUBF + vs_ * 4);
        CP_COMMIT();
    }

    float acc[4][4];
    #pragma unroll
    for (int r = 0; r < 4; r++)
        #pragma unroll
        for (int cc = 0; cc < 4; cc++) acc[r][cc] = 0.f;

    for (int t = 0; t < 4; t++) {
        const float* Vb = V1s + (t & 1) * V1TILE;
        const float* Tb = Ts  + (t & 1) * TTILE;
        if (t + 1 < 4) {
            const int j0 = (t + 1) * 32;
            float* vd = V1s + ((t + 1) & 1) * V1TILE;
            float* td = Ts  + ((t + 1) & 1) * TTILE;
            #pragma unroll
            for (int k = 0; k < 8; k++) {
                int idx = k * 128 + tid;
                int o = idx >> 3, seg = idx & 7;
                cp16(vd + o * 32 + ((seg ^ ((o >> 2) & 7)) << 2),
                     v1 + (size_t)o * SUBF + j0 + seg * 4);
            }
            cp16(td + xr_ * 32 + vs_ * 4, tsrc + (size_t)xr_ * SUBF + j0 + vs_ * 4);
            CP_COMMIT();
            CP_WAIT(1);
        } else {
            CP_WAIT(0);
        }
        __syncthreads();

        #pragma unroll
        for (int j4 = 0; j4 < 8; j4++) {
            float4 tv[4];
            #pragma unroll
            for (int r = 0; r < 4; r++)
                tv[r] = *(const float4*)(Tb + (r0 + r) * 32 + j4 * 4);   // broadcast
            const int j4s = (j4 ^ swz) << 2;
            #pragma unroll
            for (int cc = 0; cc < 4; cc++) {
                float4 v = *(const float4*)(Vb + (4 * lane + cc) * 32 + j4s);
                #pragma unroll
                for (int r = 0; r < 4; r++)
                    acc[r][cc] += v.x * tv[r].x + v.y * tv[r].y
                                + v.z * tv[r].z + v.w * tv[r].w;
            }
        }
        __syncthreads();
    }

    #pragma unroll
    for (int r = 0; r < 4; r++) {
        if (r0 + r < m) {
            float4 o = make_float4(acc[r][0], acc[r][1], acc[r][2], acc[r][3]);
            *(float4*)(g_opart + (size_t)(gbase + r0 + r) * OUTF
                       + ot * 128 + 4 * lane) = o;
        }
    }
}

// ---------------- kernel 4: reduce 8 partials per batch row -----------------------
__global__ void __launch_bounds__(256) colak_reduce(float* __restrict__ out) {
    __shared__ int mp[KACT];
    const int b = blockIdx.x;
    const int tid = threadIdx.x;
    if (tid < KACT) mp[tid] = g_map[b * KACT + tid];
    __syncthreads();
    const float4* op = (const float4*)g_opart;
    float4 sum = make_float4(0.f, 0.f, 0.f, 0.f);
    #pragma unroll
    for (int k = 0; k < KACT; k++) {
        float4 v = op[(size_t)mp[k] * (OUTF / 4) + tid];
        sum.x += v.x; sum.y += v.y; sum.z += v.z; sum.w += v.w;
    }
    ((float4*)out)[(size_t)b * (OUTF / 4) + tid] = sum;
}

// ---------------- host launcher ----------------------------------------------------
extern "C" void kernel_launch(void* const* d_in, const int* in_sizes, int n_in,
                              void* d_out, int out_size) {
    const float* x  = (const float*)d_in[0];
    const float* q  = (const float*)d_in[1];
    const float* Wk = (const float*)d_in[2];
    const float* bk = (const float*)d_in[3];
    const float* V0 = (const float*)d_in[4];
    const float* V1 = (const float*)d_in[5];
    float* out = (float*)d_out;

    colak_attn<<<NB / 4, 256>>>(q, Wk, bk);
    colak_scatter<<<1, 256>>>();
    colak_T<<<dim3(MAXITEMS, KQ), 128, SMEM_T_BYTES>>>(x, V0);
    colak_Tred<<<NASG * SUBF / (256 * 4), 256>>>();
    colak_O<<<dim3(MAXITEMS, 8), 128, SMEM_O_BYTES>>>(V1);
    colak_reduce<<<NB, 256>>>(out);
}

// round 8
// speedup vs baseline: 1.5810x; 1.0353x over previous
#include <cuda_runtime.h>

#define NB    256
#define NS    64
#define KACT  8
#define INF_  1024
#define OUTF  1024
#define SUBF  128
#define QF    1024
#define NASG  (NB * KACT)      // 2048 total assignments (always exact)
#define KQ    8                // k-split of T across CTAs (128 i per CTA)
#define RPI   16               // rows per work item
#define MAXITEMS 192           // sum ceil(n_s/16) <= 128 + 64

// ---------------- device scratch (static globals: no runtime allocation) ----------
__device__ int   g_cnt[NS];
__device__ int   g_off[NS];
__device__ int   g_sel_s[NASG];
__device__ float g_sel_w[NASG];
__device__ int   g_asg_b[NASG];               // compacted: batch row per assignment
__device__ float g_asg_w[NASG];               // compacted: softmax weight per assignment
__device__ int   g_map[NASG];                 // (b,slot) -> compact index
__device__ int   g_work[MAXITEMS];            // (subnet<<8)|chunk
__device__ int   g_nwork;
__device__ float g_Tpart[KQ * NASG * SUBF];   // stage-1 k-partials (raw sums), 8 MB
__device__ float g_T[(NASG + RPI) * SUBF];    // reduced, weight-applied (+pad rows)
__device__ float g_opart[NASG * OUTF];        // 8 MB partial outputs

// ---------------- cp.async helpers ------------------------------------------------
__device__ __forceinline__ void cp16(void* s, const void* g) {
    unsigned sa = (unsigned)__cvta_generic_to_shared(s);
    asm volatile("cp.async.cg.shared.global [%0], [%1], 16;\n" :: "r"(sa), "l"(g));
}
#define CP_COMMIT()  asm volatile("cp.async.commit_group;\n")
#define CP_WAIT(n)   asm volatile("cp.async.wait_group %0;\n" :: "n"(n))

// ---------------- kernel 1: attention + top-8 + softmax ---------------------------
// 64 CTAs x 256 threads, 4 batch rows per CTA.
__global__ void __launch_bounds__(256) colak_attn(const float* __restrict__ q,
                                                  const float* __restrict__ Wk,
                                                  const float* __restrict__ bk) {
    __shared__ float qs[4 * QF];
    __shared__ float att[4][NS];
    const int b0   = blockIdx.x * 4;
    const int tid  = threadIdx.x;
    const int w    = tid >> 5;
    const int lane = tid & 31;

    for (int f = tid; f < 4 * (QF / 4); f += 256)
        ((float4*)qs)[f] = ((const float4*)(q + (size_t)b0 * QF))[f];
    __syncthreads();

    const float4* q4 = (const float4*)qs;
    #pragma unroll
    for (int p = 0; p < 8; p++) {
        const int s = p * 8 + w;
        const float4* wr = (const float4*)(Wk + (size_t)s * QF);
        float acc[4];
        #pragma unroll
        for (int r = 0; r < 4; r++) acc[r] = 0.f;
        #pragma unroll
        for (int i = lane; i < QF / 4; i += 32) {
            float4 a = wr[i];
            #pragma unroll
            for (int r = 0; r < 4; r++) {
                float4 c = q4[r * (QF / 4) + i];
                acc[r] += a.x * c.x + a.y * c.y + a.z * c.z + a.w * c.w;
            }
        }
        #pragma unroll
        for (int r = 0; r < 4; r++) {
            float v = acc[r];
            #pragma unroll
            for (int o = 16; o; o >>= 1) v += __shfl_xor_sync(0xffffffffu, v, o);
            if (lane == 0) att[r][s] = v + bk[s];
        }
    }
    __syncthreads();

    if (w < 4) {
        const int b = b0 + w;
        float v0 = att[w][lane], v1 = att[w][lane + 32];
        int r0 = 0, r1 = 0;
        #pragma unroll
        for (int j = 0; j < NS; j++) {
            float a = att[w][j];
            r0 += (a > v0) || (a == v0 && j < lane);
            r1 += (a > v1) || (a == v1 && j < lane + 32);
        }
        bool k0 = r0 < KACT, k1 = r1 < KACT;

        float m = fmaxf(k0 ? v0 : -1e30f, k1 ? v1 : -1e30f);
        #pragma unroll
        for (int o = 16; o; o >>= 1) m = fmaxf(m, __shfl_xor_sync(0xffffffffu, m, o));

        float e0 = k0 ? expf(v0 - m) : 0.f;
        float e1 = k1 ? expf(v1 - m) : 0.f;
        float sm = e0 + e1;
        #pragma unroll
        for (int o = 16; o; o >>= 1) sm += __shfl_xor_sync(0xffffffffu, sm, o);

        unsigned m0 = __ballot_sync(0xffffffffu, k0);
        unsigned m1 = __ballot_sync(0xffffffffu, k1);
        unsigned lt = (1u << lane) - 1u;
        int base1 = __popc(m0);
        if (k0) {
            int slot = __popc(m0 & lt);
            g_sel_s[b * KACT + slot] = lane;
            g_sel_w[b * KACT + slot] = e0 / sm;
        }
        if (k1) {
            int slot = base1 + __popc(m1 & lt);
            g_sel_s[b * KACT + slot] = lane + 32;
            g_sel_w[b * KACT + slot] = e1 / sm;
        }
    }
}

// ---------------- kernel 2: count + scans + compact + work list (one block) -------
__global__ void __launch_bounds__(256) colak_scatter() {
    __shared__ int cnt[NS], off_s[NS], fill[NS], ncoff[NS];
    const int tid = threadIdx.x;
    if (tid < NS) cnt[tid] = 0;
    __syncthreads();
    for (int idx = tid; idx < NASG; idx += 256)
        atomicAdd(&cnt[g_sel_s[idx]], 1);
    __syncthreads();

    if (tid < 32) {
        const int lane = tid;
        int a = cnt[lane], b = cnt[lane + 32];
        int ia = a, ib = b;
        #pragma unroll
        for (int d = 1; d < 32; d <<= 1) {
            int t = __shfl_up_sync(0xffffffffu, ia, d); if (lane >= d) ia += t;
        }
        int tota = __shfl_sync(0xffffffffu, ia, 31);
        #pragma unroll
        for (int d = 1; d < 32; d <<= 1) {
            int t = __shfl_up_sync(0xffffffffu, ib, d); if (lane >= d) ib += t;
        }
        off_s[lane]      = ia - a;
        off_s[lane + 32] = tota + ib - b;

        int nca = (a + RPI - 1) / RPI, ncb = (b + RPI - 1) / RPI;
        int inca = nca, incb = ncb;
        #pragma unroll
        for (int d = 1; d < 32; d <<= 1) {
            int t = __shfl_up_sync(0xffffffffu, inca, d); if (lane >= d) inca += t;
        }
        int totnca = __shfl_sync(0xffffffffu, inca, 31);
        #pragma unroll
        for (int d = 1; d < 32; d <<= 1) {
            int t = __shfl_up_sync(0xffffffffu, incb, d); if (lane >= d) incb += t;
        }
        ncoff[lane]      = inca - nca;
        ncoff[lane + 32] = totnca + incb - ncb;
        if (lane == 31) g_nwork = totnca + incb;
    }
    __syncthreads();

    if (tid < NS) {
        g_cnt[tid] = cnt[tid]; g_off[tid] = off_s[tid]; fill[tid] = off_s[tid];
        int base = ncoff[tid];
        int nc = (cnt[tid] + RPI - 1) / RPI;
        for (int c = 0; c < nc; c++) g_work[base + c] = (tid << 8) | c;
    }
    __syncthreads();
    for (int idx = tid; idx < NASG; idx += 256) {
        int s = g_sel_s[idx];
        int p = atomicAdd(&fill[s], 1);
        g_asg_b[p] = idx >> 3;
        g_asg_w[p] = g_sel_w[idx];
        g_map[idx] = p;
    }
}

// ---------------- kernel T: stage 1 (k-eighth per CTA) ----------------------------
// CTA = (16 asg rows of one subnet, 128-wide i-slice). 128 threads, 4 warps.
// Warp w owns rows 4w..4w+3; thread owns 4r x 4j (j = 4*lane+cc). 16 acc regs.
// smem: V0 tile [128j][32i] swizzled db (32KB) + X [16r][32i] db (4KB) = 36KB.
#define V0TILE (128 * 32)
#define XTILE  (RPI * 32)
#define SMEM_T_BYTES ((2 * V0TILE + 2 * XTILE) * 4)
#define TKTILES 4     // 128 i per CTA / 32 per tile

__global__ void __launch_bounds__(128, 6) colak_T(const float* __restrict__ x,
                                                  const float* __restrict__ V0) {
    if ((int)blockIdx.x >= g_nwork) return;
    const int item = g_work[blockIdx.x];
    const int s  = item >> 8;
    const int c  = item & 255;
    const int kq = blockIdx.y;            // 0..KQ-1
    const int n  = g_cnt[s];
    const int m  = min(RPI, n - c * RPI);
    const int gbase = g_off[s] + c * RPI;

    extern __shared__ float smem[];
    float* V0s = smem;                    // 2 x [128][32]
    float* Xs  = smem + 2 * V0TILE;       // 2 x [16][32]
    __shared__ int rows[RPI];

    const int tid  = threadIdx.x;
    const int w    = tid >> 5;
    const int lane = tid & 31;
    const int r0   = w * 4;
    const int swz  = lane & 7;

    if (tid < RPI) rows[tid] = g_asg_b[gbase + min(tid, m - 1)];
    __syncthreads();

    const float* v0 = V0 + (size_t)s * SUBF * INF_;
    const int ibase = kq * 128;
    const int xr_ = tid >> 3;             // X staging: row 0..15
    const int vs_ = tid & 7;              // seg 0..7
    const float* xrow = x + (size_t)rows[xr_] * INF_;

    // prefetch tile 0
    {
        #pragma unroll
        for (int k = 0; k < 8; k++) {
            int idx = k * 128 + tid;
            int j = idx >> 3, seg = idx & 7;
            cp16(V0s + j * 32 + ((seg ^ ((j >> 2) & 7)) << 2),
                 v0 + (size_t)j * INF_ + ibase + seg * 4);
        }
        cp16(Xs + xr_ * 32 + vs_ * 4, xrow + ibase + vs_ * 4);
        CP_COMMIT();
    }

    float acc[4][4];
    #pragma unroll
    for (int r = 0; r < 4; r++)
        #pragma unroll
        for (int cc = 0; cc < 4; cc++) acc[r][cc] = 0.f;

    for (int t = 0; t < TKTILES; t++) {
        const float* Vb = V0s + (t & 1) * V0TILE;
        const float* Xb = Xs  + (t & 1) * XTILE;
        if (t + 1 < TKTILES) {
            const int i0 = ibase + (t + 1) * 32;
            float* vd = V0s + ((t + 1) & 1) * V0TILE;
            float* xd = Xs  + ((t + 1) & 1) * XTILE;
            #pragma unroll
            for (int k = 0; k < 8; k++) {
                int idx = k * 128 + tid;
                int j = idx >> 3, seg = idx & 7;
                cp16(vd + j * 32 + ((seg ^ ((j >> 2) & 7)) << 2),
                     v0 + (size_t)j * INF_ + i0 + seg * 4);
            }
            cp16(xd + xr_ * 32 + vs_ * 4, xrow + i0 + vs_ * 4);
            CP_COMMIT();
            CP_WAIT(1);
        } else {
            CP_WAIT(0);
        }
        __syncthreads();

        #pragma unroll
        for (int i4 = 0; i4 < 8; i4++) {
            float4 xv[4];
            #pragma unroll
            for (int r = 0; r < 4; r++)
                xv[r] = *(const float4*)(Xb + (r0 + r) * 32 + i4 * 4);   // broadcast
            const int i4s = (i4 ^ swz) << 2;
            #pragma unroll
            for (int cc = 0; cc < 4; cc++) {
                float4 v = *(const float4*)(Vb + (4 * lane + cc) * 32 + i4s);
                #pragma unroll
                for (int r = 0; r < 4; r++)
                    acc[r][cc] += v.x * xv[r].x + v.y * xv[r].y
                                + v.z * xv[r].z + v.w * xv[r].w;
            }
        }
        __syncthreads();   // all warps done with buf before next prefetch overwrites
    }

    float* dst = g_Tpart + (size_t)kq * NASG * SUBF;
    #pragma unroll
    for (int r = 0; r < 4; r++) {
        if (r0 + r < m) {
            float4 o = make_float4(acc[r][0], acc[r][1], acc[r][2], acc[r][3]);
            *(float4*)(dst + (size_t)(gbase + r0 + r) * SUBF + 4 * lane) = o;
        }
    }
}

// ---------------- kernel Tred: sum 8 k-partials, apply weight ---------------------
__global__ void __launch_bounds__(256) colak_Tred() {
    const int idx = blockIdx.x * 256 + threadIdx.x;   // 0..65535
    const int row = idx >> 5, qd = idx & 31;
    float4 a = *(const float4*)(g_Tpart + (size_t)row * SUBF + qd * 4);
    #pragma unroll
    for (int h = 1; h < KQ; h++) {
        float4 b = *(const float4*)(g_Tpart + ((size_t)h * NASG + row) * SUBF + qd * 4);
        a.x += b.x; a.y += b.y; a.z += b.z; a.w += b.w;
    }
    const float wt = g_asg_w[row];
    a.x *= wt; a.y *= wt; a.z *= wt; a.w *= wt;
    *(float4*)(g_T + (size_t)row * SUBF + qd * 4) = a;
}

// ---------------- kernel O: stage 2  O[r][o] = sum_j T[r][j]*V1[s][o][j] ----------
// CTA = (16 asg rows, 128-wide o-tile). 128 threads. k-tiles of 32 j, db cp.async.
// smem: V1 tile [128o][32j] swizzled db (32KB) + T [16r][32j] db (4KB) = 36KB.
#define V1TILE (128 * 32)
#define TTILE  (RPI * 32)
#define SMEM_O_BYTES ((2 * V1TILE + 2 * TTILE) * 4)

__global__ void __launch_bounds__(128, 6) colak_O(const float* __restrict__ V1) {
    if ((int)blockIdx.x >= g_nwork) return;
    const int item = g_work[blockIdx.x];
    const int s  = item >> 8;
    const int c  = item & 255;
    const int ot = blockIdx.y;            // 0..7
    const int n  = g_cnt[s];
    const int m  = min(RPI, n - c * RPI);
    const int gbase = g_off[s] + c * RPI;

    extern __shared__ float smem[];
    float* V1s = smem;                    // 2 x [128][32]
    float* Ts  = smem + 2 * V1TILE;       // 2 x [16][32]

    const int tid  = threadIdx.x;
    const int w    = tid >> 5;
    const int lane = tid & 31;
    const int r0   = w * 4;
    const int swz  = lane & 7;

    const float* v1 = V1 + (size_t)s * OUTF * SUBF + (size_t)ot * 128 * SUBF;
    const float* tsrc = g_T + (size_t)gbase * SUBF;
    const int xr_ = tid >> 3;
    const int vs_ = tid & 7;

    // prefetch tile 0 (j0 = 0)
    {
        #pragma unroll
        for (int k = 0; k < 8; k++) {
            int idx = k * 128 + tid;
            int o = idx >> 3, seg = idx & 7;
            cp16(V1s + o * 32 + ((seg ^ ((o >> 2) & 7)) << 2),
                 v1 + (size_t)o * SUBF + seg * 4);
        }
        cp16(Ts + xr_ * 32 + vs_ * 4, tsrc + (size_t)xr_ * SUBF + vs_ * 4);
        CP_COMMIT();
    }

    float acc[4][4];
    #pragma unroll
    for (int r = 0; r < 4; r++)
        #pragma unroll
        for (int cc = 0; cc < 4; cc++) acc[r][cc] = 0.f;

    for (int t = 0; t < 4; t++) {
        const float* Vb = V1s + (t & 1) * V1TILE;
        const float* Tb = Ts  + (t & 1) * TTILE;
        if (t + 1 < 4) {
            const int j0 = (t + 1) * 32;
            float* vd = V1s + ((t + 1) & 1) * V1TILE;
            float* td = Ts  + ((t + 1) & 1) * TTILE;
            #pragma unroll
            for (int k = 0; k < 8; k++) {
                int idx = k * 128 + tid;
                int o = idx >> 3, seg = idx & 7;
                cp16(vd + o * 32 + ((seg ^ ((o >> 2) & 7)) << 2),
                     v1 + (size_t)o * SUBF + j0 + seg * 4);
            }
            cp16(td + xr_ * 32 + vs_ * 4, tsrc + (size_t)xr_ * SUBF + j0 + vs_ * 4);
            CP_COMMIT();
            CP_WAIT(1);
        } else {
            CP_WAIT(0);
        }
        __syncthreads();

        #pragma unroll
        for (int j4 = 0; j4 < 8; j4++) {
            float4 tv[4];
            #pragma unroll
            for (int r = 0; r < 4; r++)
                tv[r] = *(const float4*)(Tb + (r0 + r) * 32 + j4 * 4);   // broadcast
            const int j4s = (j4 ^ swz) << 2;
            #pragma unroll
            for (int cc = 0; cc < 4; cc++) {
                float4 v = *(const float4*)(Vb + (4 * lane + cc) * 32 + j4s);
                #pragma unroll
                for (int r = 0; r < 4; r++)
                    acc[r][cc] += v.x * tv[r].x + v.y * tv[r].y
                                + v.z * tv[r].z + v.w * tv[r].w;
            }
        }
        __syncthreads();
    }

    #pragma unroll
    for (int r = 0; r < 4; r++) {
        if (r0 + r < m) {
            float4 o = make_float4(acc[r][0], acc[r][1], acc[r][2], acc[r][3]);
            *(float4*)(g_opart + (size_t)(gbase + r0 + r) * OUTF
                       + ot * 128 + 4 * lane) = o;
        }
    }
}

// ---------------- kernel 4: reduce 8 partials per batch row -----------------------
__global__ void __launch_bounds__(256) colak_reduce(float* __restrict__ out) {
    __shared__ int mp[KACT];
    const int b = blockIdx.x;
    const int tid = threadIdx.x;
    if (tid < KACT) mp[tid] = g_map[b * KACT + tid];
    __syncthreads();
    const float4* op = (const float4*)g_opart;
    float4 sum = make_float4(0.f, 0.f, 0.f, 0.f);
    #pragma unroll
    for (int k = 0; k < KACT; k++) {
        float4 v = op[(size_t)mp[k] * (OUTF / 4) + tid];
        sum.x += v.x; sum.y += v.y; sum.z += v.z; sum.w += v.w;
    }
    ((float4*)out)[(size_t)b * (OUTF / 4) + tid] = sum;
}

// ---------------- host launcher ----------------------------------------------------
extern "C" void kernel_launch(void* const* d_in, const int* in_sizes, int n_in,
                              void* d_out, int out_size) {
    const float* x  = (const float*)d_in[0];
    const float* q  = (const float*)d_in[1];
    const float* Wk = (const float*)d_in[2];
    const float* bk = (const float*)d_in[3];
    const float* V0 = (const float*)d_in[4];
    const float* V1 = (const float*)d_in[5];
    float* out = (float*)d_out;

    colak_attn<<<NB / 4, 256>>>(q, Wk, bk);
    colak_scatter<<<1, 256>>>();
    colak_T<<<dim3(MAXITEMS, KQ), 128, SMEM_T_BYTES>>>(x, V0);
    colak_Tred<<<NASG * SUBF / (256 * 4), 256>>>();
    colak_O<<<dim3(MAXITEMS, 8), 128, SMEM_O_BYTES>>>(V1);
    colak_reduce<<<NB, 256>>>(out);
}